// round 14
// baseline (speedup 1.0000x reference)
#include <cuda_runtime.h>
#include <cuda_fp16.h>
#include <cstdint>

#define DIM 128
#define NODES_MAX 50048
#define EDGES_MAX 800000

// ---------------- device scratch (allocation-free rule) ----------------
// g_deg_i is zero at every kernel_launch entry: zero-initialized at load, and
// fill_csr_kernel's atomic countdown restores it to exactly zero each run.
__device__ int   g_deg_i[NODES_MAX];
__device__ int   g_rowptr[NODES_MAX + 1];
__device__ int   g_csr[EDGES_MAX];
__device__ float g_invdeg[NODES_MAX];
__device__ __align__(16) float  g_S[(size_t)NODES_MAX * DIM];   // self partial (fp32)
__device__ __align__(16) float  g_S3[(size_t)NODES_MAX * 64];   // layer-3 self partial (fp32)
__device__ __align__(16) __half g_P16[(size_t)NODES_MAX * 64];  // layer-3 h@Wn3 (fp16)
__device__ __align__(16) __half g_xf16[(size_t)NODES_MAX * DIM];// fp16 activations
__device__ __align__(16) __half g_hf16[(size_t)NODES_MAX * DIM];
__device__ __align__(16) __half g_agg16[(size_t)NODES_MAX * DIM];
__device__ __align__(16) __half g_wth[6 * 16384];               // transposed [N][K] weight hi (fp16)
__device__ __align__(16) __half g_wtl[6 * 16384];               // lo parts (fp16)

// ---------------- PTX helpers (sm_80-baseline features only) ----------------
__device__ __forceinline__ uint32_t smem_to_u32(const void* p) {
    uint32_t a;
    asm("{ .reg .u64 t; cvta.to.shared.u64 t, %1; cvt.u32.u64 %0, t; }" : "=r"(a) : "l"(p));
    return a;
}
__device__ __forceinline__ void ldsm_x4(uint32_t* r, uint32_t addr) {
    asm volatile("ldmatrix.sync.aligned.m8n8.x4.shared.b16 {%0,%1,%2,%3}, [%4];"
                 : "=r"(r[0]), "=r"(r[1]), "=r"(r[2]), "=r"(r[3]) : "r"(addr));
}
__device__ __forceinline__ void mma_f16(float* d, const uint32_t* a, const uint32_t* b) {
    asm volatile(
        "mma.sync.aligned.m16n8k16.row.col.f32.f16.f16.f32 "
        "{%0,%1,%2,%3}, {%4,%5,%6,%7}, {%8,%9}, {%0,%1,%2,%3};"
        : "+f"(d[0]), "+f"(d[1]), "+f"(d[2]), "+f"(d[3])
        : "r"(a[0]), "r"(a[1]), "r"(a[2]), "r"(a[3]), "r"(b[0]), "r"(b[1]));
}
__device__ __forceinline__ void cp16(uint32_t d, const void* g) {
    asm volatile("cp.async.cg.shared.global [%0], [%1], 16;" :: "r"(d), "l"(g));
}
__device__ __forceinline__ void zero16(uint32_t d) {
    asm volatile("st.shared.v4.b32 [%0], {%1,%1,%1,%1};" :: "r"(d), "r"(0u));
}
#define CP_COMMIT() asm volatile("cp.async.commit_group;" ::: "memory")
#define CP_WAIT1()  asm volatile("cp.async.wait_group 1;" ::: "memory")
#define CP_WAIT0()  asm volatile("cp.async.wait_group 0;" ::: "memory")

// ---------------- CSR build ----------------
__global__ void deg_kernel(const int* __restrict__ dst, int* __restrict__ deg, int E) {
    int e = blockIdx.x * blockDim.x + threadIdx.x;
    if (e < E) atomicAdd(&deg[dst[e]], 1);
}
__global__ void __launch_bounds__(1024)
scan_kernel(const int* __restrict__ cnt, int* __restrict__ rowptr,
            float* __restrict__ inv, int n) {
    __shared__ int wsum[32];
    const int tid = threadIdx.x;
    const int CH = (n + 1023) / 1024;
    const int base = tid * CH;
    int s = 0;
    for (int j = 0; j < CH; ++j) { int i = base + j; if (i < n) s += __ldg(cnt + i); }
    int v = s;
#pragma unroll
    for (int o = 1; o < 32; o <<= 1) { int u = __shfl_up_sync(~0u, v, o); if ((tid & 31) >= o) v += u; }
    if ((tid & 31) == 31) wsum[tid >> 5] = v;
    __syncthreads();
    if (tid < 32) {
        int w = wsum[tid];
#pragma unroll
        for (int o = 1; o < 32; o <<= 1) { int u = __shfl_up_sync(~0u, w, o); if (tid >= o) w += u; }
        wsum[tid] = w;
    }
    __syncthreads();
    int run = (v - s) + ((tid >= 32) ? wsum[(tid >> 5) - 1] : 0);
    for (int j = 0; j < CH; ++j) {
        int i = base + j;
        if (i < n) {
            int c = __ldg(cnt + i);
            run += c;
            rowptr[i + 1] = run;
            inv[i] = 1.0f / (float)max(c, 1);
        }
    }
    if (tid == 0) rowptr[0] = 0;
}
// fill via atomic countdown on deg (restores deg to all-zero for the next replay)
__global__ void fill_csr_kernel(const int* __restrict__ src, const int* __restrict__ dst,
                                const int* __restrict__ rowptr, int* __restrict__ deg,
                                int* __restrict__ csr, int E) {
    int e = blockIdx.x * blockDim.x + threadIdx.x;
    if (e < E) {
        int d = dst[e];
        int cnt = atomicAdd(&deg[d], -1);
        csr[rowptr[d] + cnt - 1] = src[e];
    }
}

// ---------------- conversions ----------------
__global__ void split_kernel(const float* __restrict__ x, __half* __restrict__ f16, int n2) {
    int i = blockIdx.x * blockDim.x + threadIdx.x;
    if (i < n2) {
        float2 v = reinterpret_cast<const float2*>(x)[i];
        reinterpret_cast<__half2*>(f16)[i] = __floats2half2_rn(v.x, v.y);
    }
}
__global__ void wsplit_kernel(const float* W1s, const float* W1n, const float* W2s,
                              const float* W2n, const float* W3s, const float* W3n,
                              __half* __restrict__ th, __half* __restrict__ tl) {
    int i = blockIdx.x * blockDim.x + threadIdx.x;
    int m, off;
    if (i < 4 * 16384) { m = i / 16384; off = i % 16384; }
    else {
        int j = i - 4 * 16384;
        if (j >= 2 * 8192) return;
        m = 4 + j / 8192; off = j % 8192;
    }
    const float* src = (m == 0) ? W1s : (m == 1) ? W1n : (m == 2) ? W2s
                     : (m == 3) ? W2n : (m == 4) ? W3s : W3n;
    int Ncols = (m < 4) ? 128 : 64;
    int nn = off / 128, kk = off % 128;
    float v = src[kk * Ncols + nn];
    __half h = __float2half(v);
    th[m * 16384 + off] = h;
    tl[m * 16384 + off] = __float2half(v - __half2float(h));
}

// -------- atomic-free mean aggregation (fp16 gather, fp32 accumulate, fp16 out) --------
__global__ void __launch_bounds__(256)
agg_kernel(const __half* __restrict__ feat, const int* __restrict__ rowptr,
           const int* __restrict__ csr, const float* __restrict__ invdeg,
           __half* __restrict__ agg, int n) {
    long long t = (long long)blockIdx.x * blockDim.x + threadIdx.x;
    int v = (int)(t >> 5);
    if (v >= n) return;
    int lane = (int)(t & 31);
    const int co = lane * 4;

    int beg = __ldg(rowptr + v);
    int end = __ldg(rowptr + v + 1);

    float ax = 0.f, ay = 0.f, az = 0.f, aw = 0.f;
    int i = beg;
    for (; i + 4 <= end; i += 4) {
        int s0 = __ldg(csr + i + 0);
        int s1 = __ldg(csr + i + 1);
        int s2 = __ldg(csr + i + 2);
        int s3 = __ldg(csr + i + 3);
        uint2 q0 = *reinterpret_cast<const uint2*>(feat + (size_t)s0 * DIM + co);
        uint2 q1 = *reinterpret_cast<const uint2*>(feat + (size_t)s1 * DIM + co);
        uint2 q2 = *reinterpret_cast<const uint2*>(feat + (size_t)s2 * DIM + co);
        uint2 q3 = *reinterpret_cast<const uint2*>(feat + (size_t)s3 * DIM + co);
        float2 a0 = __half22float2(*reinterpret_cast<__half2*>(&q0.x));
        float2 b0 = __half22float2(*reinterpret_cast<__half2*>(&q0.y));
        float2 a1 = __half22float2(*reinterpret_cast<__half2*>(&q1.x));
        float2 b1 = __half22float2(*reinterpret_cast<__half2*>(&q1.y));
        float2 a2 = __half22float2(*reinterpret_cast<__half2*>(&q2.x));
        float2 b2 = __half22float2(*reinterpret_cast<__half2*>(&q2.y));
        float2 a3 = __half22float2(*reinterpret_cast<__half2*>(&q3.x));
        float2 b3 = __half22float2(*reinterpret_cast<__half2*>(&q3.y));
        ax += (a0.x + a1.x) + (a2.x + a3.x);
        ay += (a0.y + a1.y) + (a2.y + a3.y);
        az += (b0.x + b1.x) + (b2.x + b3.x);
        aw += (b0.y + b1.y) + (b2.y + b3.y);
    }
    for (; i < end; ++i) {
        int s0 = __ldg(csr + i);
        uint2 q0 = *reinterpret_cast<const uint2*>(feat + (size_t)s0 * DIM + co);
        float2 a0 = __half22float2(*reinterpret_cast<__half2*>(&q0.x));
        float2 b0 = __half22float2(*reinterpret_cast<__half2*>(&q0.y));
        ax += a0.x; ay += a0.y; az += b0.x; aw += b0.y;
    }
    float sc = __ldg(invdeg + v);
    reinterpret_cast<__half2*>(agg + (size_t)v * DIM)[lane * 2 + 0] = __floats2half2_rn(ax * sc, ay * sc);
    reinterpret_cast<__half2*>(agg + (size_t)v * DIM)[lane * 2 + 1] = __floats2half2_rn(az * sc, aw * sc);
}

// ------ layer-3 epilogue: out[v] = S3[v] + invdeg[v] * sum P16[s]  (fp16 gather, 64-wide) ------
__global__ void __launch_bounds__(256)
aggadd_kernel(const float* __restrict__ S, const __half* __restrict__ P,
              const int* __restrict__ rowptr, const int* __restrict__ csr,
              const float* __restrict__ invdeg, float* __restrict__ out, int n) {
    long long t = (long long)blockIdx.x * blockDim.x + threadIdx.x;
    int v = (int)(t >> 5);
    if (v >= n) return;
    int lane = (int)(t & 31);
    const int co = lane * 2;

    int beg = __ldg(rowptr + v);
    int end = __ldg(rowptr + v + 1);

    float sx = 0.f, sy = 0.f;
    int i = beg;
    for (; i + 4 <= end; i += 4) {
        int s0 = __ldg(csr + i + 0);
        int s1 = __ldg(csr + i + 1);
        int s2 = __ldg(csr + i + 2);
        int s3 = __ldg(csr + i + 3);
        float2 p0 = __half22float2(*reinterpret_cast<const __half2*>(P + (size_t)s0 * 64 + co));
        float2 p1 = __half22float2(*reinterpret_cast<const __half2*>(P + (size_t)s1 * 64 + co));
        float2 p2 = __half22float2(*reinterpret_cast<const __half2*>(P + (size_t)s2 * 64 + co));
        float2 p3 = __half22float2(*reinterpret_cast<const __half2*>(P + (size_t)s3 * 64 + co));
        sx += (p0.x + p1.x) + (p2.x + p3.x);
        sy += (p0.y + p1.y) + (p2.y + p3.y);
    }
    for (; i < end; ++i) {
        int s0 = __ldg(csr + i);
        float2 p0 = __half22float2(*reinterpret_cast<const __half2*>(P + (size_t)s0 * 64 + co));
        sx += p0.x; sy += p0.y;
    }
    float sc = __ldg(invdeg + v);
    float2 s3v = *reinterpret_cast<const float2*>(S + (size_t)v * 64 + co);
    *reinterpret_cast<float2*>(out + (size_t)v * 64 + co) =
        make_float2(s3v.x + sc * sx, s3v.y + sc * sy);
}

// ---------------- shared GEMM building blocks ----------------
__device__ __forceinline__ void load_swz(const __half* __restrict__ g, char* __restrict__ s,
                                         int rows, int t) {
    for (int i = t; i < rows * 16; i += 256) {
        int row = i >> 4, c = i & 15;
        uint4 v = *reinterpret_cast<const uint4*>(g + (size_t)row * 128 + c * 8);
        *reinterpret_cast<uint4*>(s + (size_t)row * 256 + ((c ^ (row & 7)) << 4)) = v;
    }
}
__device__ __forceinline__ void issue_1(const __half* __restrict__ a,
                                        int row0, int n, uint32_t stage, int t) {
    int valid = min(32, n - row0);
    for (int i = t; i < 512; i += 256) {
        int row = i >> 4, c = i & 15;
        uint32_t off = (uint32_t)row * 256u + (uint32_t)((c ^ (row & 7)) << 4);
        size_t goff = (size_t)(row0 + row) * 128 + c * 8;
        if (row < valid) cp16(stage + off, a + goff);
        else             zero16(stage + off);
    }
}

// ---- half-layer GEMM. MODE 0: S = A@W + b (fp32). MODE 1: h = relu(S + A@W) -> fp16 ----
template <int NOUT, int MODE>
__global__ void __launch_bounds__(256, 1)
gemm_half_kernel(const __half* __restrict__ af, const __half* __restrict__ wh,
                 const __half* __restrict__ wl, const float* __restrict__ aux,
                 float* __restrict__ outf, __half* __restrict__ of16, int n, int ntiles) {
    extern __shared__ char smem[];
    constexpr int NB = NOUT * 256;
    constexpr int WBASE = 16384;
    constexpr int NPW = NOUT / 4;
    constexpr int NT = NPW / 8;
    const uint32_t sb = smem_to_u32(smem);
    const uint32_t wb = sb + WBASE;
    const int t = threadIdx.x, lane = t & 31, wid = t >> 5;

    load_swz(wh, smem + WBASE,      NOUT, t);
    load_swz(wl, smem + WBASE + NB, NOUT, t);

    const int rhalf = (wid & 1) * 16;
    const int n0 = (wid >> 1) * NPW;
    const int arowl = rhalf + (lane & 15);
    const int akh = lane >> 4;
    const int browl = ((lane >> 4) << 3) + (lane & 7);
    const int bkh = (lane >> 3) & 1;

    float breg[NT][2];
    if (MODE == 0) {
#pragma unroll
        for (int nt = 0; nt < NT; ++nt) {
            int c = n0 + nt * 8 + (lane & 3) * 2;
            breg[nt][0] = __ldg(aux + c);
            breg[nt][1] = __ldg(aux + c + 1);
        }
    }

    int tile = blockIdx.x, buf = 0;
    issue_1(af, tile * 32, n, sb, t);
    CP_COMMIT();

    for (; tile < ntiles; tile += gridDim.x) {
        const int nxt = tile + gridDim.x;
        if (nxt < ntiles) {
            issue_1(af, nxt * 32, n, sb + (uint32_t)(buf ^ 1) * 8192u, t);
            CP_COMMIT();
            CP_WAIT1();
        } else {
            CP_WAIT0();
        }
        __syncthreads();

        const uint32_t ab = sb + (uint32_t)buf * 8192u;
        float acc[NT][4];
#pragma unroll
        for (int q = 0; q < NT; ++q) { acc[q][0] = acc[q][1] = acc[q][2] = acc[q][3] = 0.f; }

#pragma unroll
        for (int ks = 0; ks < 8; ++ks) {
            uint32_t ac = (uint32_t)((2 * ks + akh) ^ (arowl & 7));
            uint32_t aoff = (uint32_t)arowl * 256u + (ac << 4);
            uint32_t A[4];
            ldsm_x4(A, ab + aoff);
#pragma unroll
            for (int np = 0; np < NT / 2; ++np) {
                int brow = n0 + np * 16 + browl;
                uint32_t bc = (uint32_t)((2 * ks + bkh) ^ (brow & 7));
                uint32_t boff = (uint32_t)brow * 256u + (bc << 4);
                uint32_t Bh[4], Bl[4];
                ldsm_x4(Bh, wb + boff);
                ldsm_x4(Bl, wb + (uint32_t)NB + boff);
                float* a0 = acc[np * 2];
                float* a1 = acc[np * 2 + 1];
                mma_f16(a0, A, Bh);  mma_f16(a1, A, Bh + 2);
                mma_f16(a0, A, Bl);  mma_f16(a1, A, Bl + 2);
            }
        }

        const int r0 = tile * 32 + rhalf + (lane >> 2);
        const int r1 = r0 + 8;
#pragma unroll
        for (int nt = 0; nt < NT; ++nt) {
            int c = n0 + nt * 8 + (lane & 3) * 2;
            float v0 = acc[nt][0], v1 = acc[nt][1], v2 = acc[nt][2], v3 = acc[nt][3];
            if (MODE == 0) {
                v0 += breg[nt][0]; v1 += breg[nt][1];
                v2 += breg[nt][0]; v3 += breg[nt][1];
                if (r0 < n)
                    *reinterpret_cast<float2*>(outf + (size_t)r0 * NOUT + c) = make_float2(v0, v1);
                if (r1 < n)
                    *reinterpret_cast<float2*>(outf + (size_t)r1 * NOUT + c) = make_float2(v2, v3);
            } else {
                if (r0 < n) {
                    float2 s = *reinterpret_cast<const float2*>(aux + (size_t)r0 * NOUT + c);
                    v0 = fmaxf(v0 + s.x, 0.f); v1 = fmaxf(v1 + s.y, 0.f);
                    *reinterpret_cast<__half2*>(of16 + (size_t)r0 * NOUT + c) = __floats2half2_rn(v0, v1);
                }
                if (r1 < n) {
                    float2 s = *reinterpret_cast<const float2*>(aux + (size_t)r1 * NOUT + c);
                    v2 = fmaxf(v2 + s.x, 0.f); v3 = fmaxf(v3 + s.y, 0.f);
                    *reinterpret_cast<__half2*>(of16 + (size_t)r1 * NOUT + c) = __floats2half2_rn(v2, v3);
                }
            }
        }
        __syncthreads();
        buf ^= 1;
    }
}

// ---- layer-3 dual GEMM: S = X@Ws + b (fp32), P = X@Wn (fp16), A tiles loaded once ----
__global__ void __launch_bounds__(256, 1)
gemm3_dual_kernel(const __half* __restrict__ xf,
                  const __half* __restrict__ wsh, const __half* __restrict__ wsl,
                  const __half* __restrict__ wnh, const __half* __restrict__ wnl,
                  const float* __restrict__ bias, float* __restrict__ S,
                  __half* __restrict__ P, int n, int ntiles) {
    extern __shared__ char smem[];
    constexpr int NB = 64 * 256;
    constexpr int WBASE = 16384;
    const uint32_t sb = smem_to_u32(smem);
    const uint32_t wb = sb + WBASE;
    const int t = threadIdx.x, lane = t & 31, wid = t >> 5;

    load_swz(wsh, smem + WBASE,          64, t);
    load_swz(wsl, smem + WBASE + NB,     64, t);
    load_swz(wnh, smem + WBASE + 2 * NB, 64, t);
    load_swz(wnl, smem + WBASE + 3 * NB, 64, t);

    const int rhalf = (wid & 1) * 16;
    const int n0 = (wid >> 1) * 16;
    const int arowl = rhalf + (lane & 15);
    const int akh = lane >> 4;
    const int browl = ((lane >> 4) << 3) + (lane & 7);
    const int bkh = (lane >> 3) & 1;
    const int brow = n0 + browl;

    float breg[2][2];
#pragma unroll
    for (int nt = 0; nt < 2; ++nt) {
        int c = n0 + nt * 8 + (lane & 3) * 2;
        breg[nt][0] = __ldg(bias + c);
        breg[nt][1] = __ldg(bias + c + 1);
    }

    int tile = blockIdx.x, buf = 0;
    issue_1(xf, tile * 32, n, sb, t);
    CP_COMMIT();

    for (; tile < ntiles; tile += gridDim.x) {
        const int nxt = tile + gridDim.x;
        if (nxt < ntiles) {
            issue_1(xf, nxt * 32, n, sb + (uint32_t)(buf ^ 1) * 8192u, t);
            CP_COMMIT();
            CP_WAIT1();
        } else {
            CP_WAIT0();
        }
        __syncthreads();

        const uint32_t ab = sb + (uint32_t)buf * 8192u;
        float accS[2][4], accP[2][4];
#pragma unroll
        for (int q = 0; q < 2; ++q) {
            accS[q][0] = accS[q][1] = accS[q][2] = accS[q][3] = 0.f;
            accP[q][0] = accP[q][1] = accP[q][2] = accP[q][3] = 0.f;
        }

#pragma unroll
        for (int ks = 0; ks < 8; ++ks) {
            uint32_t ac = (uint32_t)((2 * ks + akh) ^ (arowl & 7));
            uint32_t aoff = (uint32_t)arowl * 256u + (ac << 4);
            uint32_t A[4];
            ldsm_x4(A, ab + aoff);
            uint32_t bc = (uint32_t)((2 * ks + bkh) ^ (brow & 7));
            uint32_t boff = (uint32_t)brow * 256u + (bc << 4);
            uint32_t Bsh[4], Bsl[4], Bnh[4], Bnl[4];
            ldsm_x4(Bsh, wb + boff);
            ldsm_x4(Bsl, wb + (uint32_t)NB + boff);
            ldsm_x4(Bnh, wb + (uint32_t)(2 * NB) + boff);
            ldsm_x4(Bnl, wb + (uint32_t)(3 * NB) + boff);
            mma_f16(accS[0], A, Bsh);  mma_f16(accS[1], A, Bsh + 2);
            mma_f16(accP[0], A, Bnh);  mma_f16(accP[1], A, Bnh + 2);
            mma_f16(accS[0], A, Bsl);  mma_f16(accS[1], A, Bsl + 2);
            mma_f16(accP[0], A, Bnl);  mma_f16(accP[1], A, Bnl + 2);
        }

        const int r0 = tile * 32 + rhalf + (lane >> 2);
        const int r1 = r0 + 8;
#pragma unroll
        for (int nt = 0; nt < 2; ++nt) {
            int c = n0 + nt * 8 + (lane & 3) * 2;
            if (r0 < n) {
                *reinterpret_cast<float2*>(S + (size_t)r0 * 64 + c) =
                    make_float2(accS[nt][0] + breg[nt][0], accS[nt][1] + breg[nt][1]);
                *reinterpret_cast<__half2*>(P + (size_t)r0 * 64 + c) =
                    __floats2half2_rn(accP[nt][0], accP[nt][1]);
            }
            if (r1 < n) {
                *reinterpret_cast<float2*>(S + (size_t)r1 * 64 + c) =
                    make_float2(accS[nt][2] + breg[nt][0], accS[nt][3] + breg[nt][1]);
                *reinterpret_cast<__half2*>(P + (size_t)r1 * 64 + c) =
                    __floats2half2_rn(accP[nt][2], accP[nt][3]);
            }
        }
        __syncthreads();
        buf ^= 1;
    }
}

// ---------------- launch ----------------
extern "C" void kernel_launch(void* const* d_in, const int* in_sizes, int n_in,
                              void* d_out, int out_size) {
    const float* x   = (const float*)d_in[0];
    const int*   src = (const int*)d_in[1];
    const int*   dst = (const int*)d_in[2];
    const float* Ws1 = (const float*)d_in[3];
    const float* b1  = (const float*)d_in[4];
    const float* Wn1 = (const float*)d_in[5];
    const float* Ws2 = (const float*)d_in[6];
    const float* b2  = (const float*)d_in[7];
    const float* Wn2 = (const float*)d_in[8];
    const float* Ws3 = (const float*)d_in[9];
    const float* b3  = (const float*)d_in[10];
    const float* Wn3 = (const float*)d_in[11];

    const int N = in_sizes[0] / DIM;
    const int E = in_sizes[1];
    float* out = (float*)d_out;

    int *deg_i, *rowptr, *csr;
    float *invdeg, *S, *S3;
    __half *P16, *xf16, *hf16, *agg16, *wth, *wtl;
    cudaGetSymbolAddress((void**)&deg_i,  g_deg_i);
    cudaGetSymbolAddress((void**)&rowptr, g_rowptr);
    cudaGetSymbolAddress((void**)&csr,    g_csr);
    cudaGetSymbolAddress((void**)&invdeg, g_invdeg);
    cudaGetSymbolAddress((void**)&S,      g_S);
    cudaGetSymbolAddress((void**)&S3,     g_S3);
    cudaGetSymbolAddress((void**)&P16,    g_P16);
    cudaGetSymbolAddress((void**)&xf16,   g_xf16);
    cudaGetSymbolAddress((void**)&hf16,   g_hf16);
    cudaGetSymbolAddress((void**)&agg16,  g_agg16);
    cudaGetSymbolAddress((void**)&wth,    g_wth);
    cudaGetSymbolAddress((void**)&wtl,    g_wtl);

    // one-time host-side setup (runs on the non-captured correctness call first)
    static cudaStream_t s1 = nullptr;
    static cudaEvent_t evf, evsp, ea1, eh1, ea2;
    if (!s1) {
        cudaStreamCreateWithFlags(&s1, cudaStreamNonBlocking);
        cudaEventCreateWithFlags(&evf,  cudaEventDisableTiming);
        cudaEventCreateWithFlags(&evsp, cudaEventDisableTiming);
        cudaEventCreateWithFlags(&ea1,  cudaEventDisableTiming);
        cudaEventCreateWithFlags(&eh1,  cudaEventDisableTiming);
        cudaEventCreateWithFlags(&ea2,  cudaEventDisableTiming);
    }

    const int SMH = 16384 + 2 * 128 * 256;   // 81920 (half GEMMs)
    const int SM3 = 16384 + 4 * 64 * 256;    // 81920 (layer-3 dual)
    cudaFuncSetAttribute(gemm_half_kernel<128, 0>,
                         cudaFuncAttributeMaxDynamicSharedMemorySize, SMH);
    cudaFuncSetAttribute(gemm_half_kernel<128, 1>,
                         cudaFuncAttributeMaxDynamicSharedMemorySize, SMH);
    cudaFuncSetAttribute(gemm3_dual_kernel,
                         cudaFuncAttributeMaxDynamicSharedMemorySize, SM3);

    const int nb_edges = (E + 255) / 256;
    const int nb_agg   = (int)(((long long)N * 32 + 255) / 256);
    const int ntiles   = (N + 31) / 32;
    const int GRIDG    = 152;   // 1 persistent CTA per SM (2/SM measured worse: R13)

    // ---- fork: s1 builds CSR while s0 does conversions; agg1 (s1) waits on the convert ----
    cudaEventRecord(evf, 0);
    cudaStreamWaitEvent(s1, evf, 0);

    // deg_i is all-zero at entry (zero-init + fill_csr countdown restores it)
    deg_kernel<<<nb_edges, 256, 0, s1>>>(dst, deg_i, E);
    scan_kernel<<<1, 1024, 0, s1>>>(deg_i, rowptr, invdeg, N);
    fill_csr_kernel<<<nb_edges, 256, 0, s1>>>(src, dst, rowptr, deg_i, csr, E);

    split_kernel<<<(N * DIM / 2 + 255) / 256, 256>>>(x, xf16, N * DIM / 2);
    cudaEventRecord(evsp, 0);
    wsplit_kernel<<<(81920 + 255) / 256, 256>>>(Ws1, Wn1, Ws2, Wn2, Ws3, Wn3, wth, wtl);

    cudaStreamWaitEvent(s1, evsp, 0);
    agg_kernel<<<nb_agg, 256, 0, s1>>>(xf16, rowptr, csr, invdeg, agg16, N);
    cudaEventRecord(ea1, s1);

    // s0: layer-1 self GEMM overlaps with CSR + agg1
    gemm_half_kernel<128, 0><<<GRIDG, 256, SMH>>>(
        xf16, wth + 0 * 16384, wtl + 0 * 16384, b1, S, nullptr, N, ntiles);

    // ---- join: layer-1 neigh ----
    cudaStreamWaitEvent(0, ea1, 0);
    gemm_half_kernel<128, 1><<<GRIDG, 256, SMH>>>(
        agg16, wth + 1 * 16384, wtl + 1 * 16384, S, nullptr, hf16, N, ntiles);
    cudaEventRecord(eh1, 0);

    // ---- layer 2: agg2 (s1) || self2 (s0), join for neigh2 ----
    cudaStreamWaitEvent(s1, eh1, 0);
    agg_kernel<<<nb_agg, 256, 0, s1>>>(hf16, rowptr, csr, invdeg, agg16, N);
    cudaEventRecord(ea2, s1);

    gemm_half_kernel<128, 0><<<GRIDG, 256, SMH>>>(
        hf16, wth + 2 * 16384, wtl + 2 * 16384, b2, S, nullptr, N, ntiles);

    cudaStreamWaitEvent(0, ea2, 0);
    gemm_half_kernel<128, 1><<<GRIDG, 256, SMH>>>(
        agg16, wth + 3 * 16384, wtl + 3 * 16384, S, nullptr, hf16, N, ntiles);

    // ---- layer 3: lin-before-mp (matches reference) ----
    gemm3_dual_kernel<<<GRIDG, 256, SM3>>>(
        hf16,
        wth + 4 * 16384, wtl + 4 * 16384, wth + 5 * 16384, wtl + 5 * 16384,
        b3, S3, P16, N, ntiles);
    aggadd_kernel<<<nb_agg, 256>>>(S3, P16, rowptr, csr, invdeg, out, N);
}

// round 15
// speedup vs baseline: 1.0778x; 1.0778x over previous
#include <cuda_runtime.h>
#include <cuda_fp16.h>
#include <cstdint>

#define DIM 128
#define NODES_MAX 50048
#define EDGES_MAX 800000

// ---------------- device scratch (allocation-free rule) ----------------
// g_deg_i is zero at every kernel_launch entry: zero-initialized at load, and
// fill_csr_kernel's atomic countdown restores it to exactly zero each run.
__device__ int   g_deg_i[NODES_MAX];
__device__ int   g_rowptr[NODES_MAX + 1];
__device__ int   g_csr[EDGES_MAX];
__device__ float g_invdeg[NODES_MAX];
__device__ __align__(16) float  g_S1[(size_t)NODES_MAX * DIM];  // layer-1 self partial (fp32)
__device__ __align__(16) float  g_S3[(size_t)NODES_MAX * 64];   // layer-3 self partial (fp32)
__device__ __align__(16) __half g_P16[(size_t)NODES_MAX * 64];  // layer-3 h@Wn3 (fp16)
__device__ __align__(16) __half g_xf16[(size_t)NODES_MAX * DIM];// fp16 activations
__device__ __align__(16) __half g_hf16[(size_t)NODES_MAX * DIM];
__device__ __align__(16) __half g_agg16[(size_t)NODES_MAX * DIM];
__device__ __align__(16) __half g_wth[6 * 16384];               // transposed [N][K] weight hi (fp16)
__device__ __align__(16) __half g_wtl[6 * 16384];               // lo parts (fp16)

// ---------------- PTX helpers (sm_80-baseline features only) ----------------
__device__ __forceinline__ uint32_t smem_to_u32(const void* p) {
    uint32_t a;
    asm("{ .reg .u64 t; cvta.to.shared.u64 t, %1; cvt.u32.u64 %0, t; }" : "=r"(a) : "l"(p));
    return a;
}
__device__ __forceinline__ void ldsm_x4(uint32_t* r, uint32_t addr) {
    asm volatile("ldmatrix.sync.aligned.m8n8.x4.shared.b16 {%0,%1,%2,%3}, [%4];"
                 : "=r"(r[0]), "=r"(r[1]), "=r"(r[2]), "=r"(r[3]) : "r"(addr));
}
__device__ __forceinline__ void mma_f16(float* d, const uint32_t* a, const uint32_t* b) {
    asm volatile(
        "mma.sync.aligned.m16n8k16.row.col.f32.f16.f16.f32 "
        "{%0,%1,%2,%3}, {%4,%5,%6,%7}, {%8,%9}, {%0,%1,%2,%3};"
        : "+f"(d[0]), "+f"(d[1]), "+f"(d[2]), "+f"(d[3])
        : "r"(a[0]), "r"(a[1]), "r"(a[2]), "r"(a[3]), "r"(b[0]), "r"(b[1]));
}
__device__ __forceinline__ void cp16(uint32_t d, const void* g) {
    asm volatile("cp.async.cg.shared.global [%0], [%1], 16;" :: "r"(d), "l"(g));
}
__device__ __forceinline__ void zero16(uint32_t d) {
    asm volatile("st.shared.v4.b32 [%0], {%1,%1,%1,%1};" :: "r"(d), "r"(0u));
}
#define CP_COMMIT() asm volatile("cp.async.commit_group;" ::: "memory")
#define CP_WAIT1()  asm volatile("cp.async.wait_group 1;" ::: "memory")
#define CP_WAIT0()  asm volatile("cp.async.wait_group 0;" ::: "memory")

// ---------------- CSR build ----------------
__global__ void deg_kernel(const int* __restrict__ dst, int* __restrict__ deg, int E) {
    int e = blockIdx.x * blockDim.x + threadIdx.x;
    if (e < E) atomicAdd(&deg[dst[e]], 1);
}
__global__ void __launch_bounds__(1024)
scan_kernel(const int* __restrict__ cnt, int* __restrict__ rowptr,
            float* __restrict__ inv, int n) {
    __shared__ int wsum[32];
    const int tid = threadIdx.x;
    const int CH = (n + 1023) / 1024;
    const int base = tid * CH;
    int s = 0;
    for (int j = 0; j < CH; ++j) { int i = base + j; if (i < n) s += __ldg(cnt + i); }
    int v = s;
#pragma unroll
    for (int o = 1; o < 32; o <<= 1) { int u = __shfl_up_sync(~0u, v, o); if ((tid & 31) >= o) v += u; }
    if ((tid & 31) == 31) wsum[tid >> 5] = v;
    __syncthreads();
    if (tid < 32) {
        int w = wsum[tid];
#pragma unroll
        for (int o = 1; o < 32; o <<= 1) { int u = __shfl_up_sync(~0u, w, o); if (tid >= o) w += u; }
        wsum[tid] = w;
    }
    __syncthreads();
    int run = (v - s) + ((tid >= 32) ? wsum[(tid >> 5) - 1] : 0);
    for (int j = 0; j < CH; ++j) {
        int i = base + j;
        if (i < n) {
            int c = __ldg(cnt + i);
            run += c;
            rowptr[i + 1] = run;
            inv[i] = 1.0f / (float)max(c, 1);
        }
    }
    if (tid == 0) rowptr[0] = 0;
}
// fill via atomic countdown on deg (restores deg to all-zero for the next replay)
__global__ void fill_csr_kernel(const int* __restrict__ src, const int* __restrict__ dst,
                                const int* __restrict__ rowptr, int* __restrict__ deg,
                                int* __restrict__ csr, int E) {
    int e = blockIdx.x * blockDim.x + threadIdx.x;
    if (e < E) {
        int d = dst[e];
        int cnt = atomicAdd(&deg[d], -1);
        csr[rowptr[d] + cnt - 1] = src[e];
    }
}

// ---------------- conversions ----------------
__global__ void split_kernel(const float* __restrict__ x, __half* __restrict__ f16, int n2) {
    int i = blockIdx.x * blockDim.x + threadIdx.x;
    if (i < n2) {
        float2 v = reinterpret_cast<const float2*>(x)[i];
        reinterpret_cast<__half2*>(f16)[i] = __floats2half2_rn(v.x, v.y);
    }
}
__global__ void wsplit_kernel(const float* W1s, const float* W1n, const float* W2s,
                              const float* W2n, const float* W3s, const float* W3n,
                              __half* __restrict__ th, __half* __restrict__ tl) {
    int i = blockIdx.x * blockDim.x + threadIdx.x;
    int m, off;
    if (i < 4 * 16384) { m = i / 16384; off = i % 16384; }
    else {
        int j = i - 4 * 16384;
        if (j >= 2 * 8192) return;
        m = 4 + j / 8192; off = j % 8192;
    }
    const float* src = (m == 0) ? W1s : (m == 1) ? W1n : (m == 2) ? W2s
                     : (m == 3) ? W2n : (m == 4) ? W3s : W3n;
    int Ncols = (m < 4) ? 128 : 64;
    int nn = off / 128, kk = off % 128;
    float v = src[kk * Ncols + nn];
    __half h = __float2half(v);
    th[m * 16384 + off] = h;
    tl[m * 16384 + off] = __float2half(v - __half2float(h));
}

// -------- atomic-free mean aggregation (fp16 gather, fp32 accumulate, fp16 out) --------
__global__ void __launch_bounds__(256)
agg_kernel(const __half* __restrict__ feat, const int* __restrict__ rowptr,
           const int* __restrict__ csr, const float* __restrict__ invdeg,
           __half* __restrict__ agg, int n) {
    long long t = (long long)blockIdx.x * blockDim.x + threadIdx.x;
    int v = (int)(t >> 5);
    if (v >= n) return;
    int lane = (int)(t & 31);
    const int co = lane * 4;

    int beg = __ldg(rowptr + v);
    int end = __ldg(rowptr + v + 1);

    float ax = 0.f, ay = 0.f, az = 0.f, aw = 0.f;
    int i = beg;
    for (; i + 4 <= end; i += 4) {
        int s0 = __ldg(csr + i + 0);
        int s1 = __ldg(csr + i + 1);
        int s2 = __ldg(csr + i + 2);
        int s3 = __ldg(csr + i + 3);
        uint2 q0 = *reinterpret_cast<const uint2*>(feat + (size_t)s0 * DIM + co);
        uint2 q1 = *reinterpret_cast<const uint2*>(feat + (size_t)s1 * DIM + co);
        uint2 q2 = *reinterpret_cast<const uint2*>(feat + (size_t)s2 * DIM + co);
        uint2 q3 = *reinterpret_cast<const uint2*>(feat + (size_t)s3 * DIM + co);
        float2 a0 = __half22float2(*reinterpret_cast<__half2*>(&q0.x));
        float2 b0 = __half22float2(*reinterpret_cast<__half2*>(&q0.y));
        float2 a1 = __half22float2(*reinterpret_cast<__half2*>(&q1.x));
        float2 b1 = __half22float2(*reinterpret_cast<__half2*>(&q1.y));
        float2 a2 = __half22float2(*reinterpret_cast<__half2*>(&q2.x));
        float2 b2 = __half22float2(*reinterpret_cast<__half2*>(&q2.y));
        float2 a3 = __half22float2(*reinterpret_cast<__half2*>(&q3.x));
        float2 b3 = __half22float2(*reinterpret_cast<__half2*>(&q3.y));
        ax += (a0.x + a1.x) + (a2.x + a3.x);
        ay += (a0.y + a1.y) + (a2.y + a3.y);
        az += (b0.x + b1.x) + (b2.x + b3.x);
        aw += (b0.y + b1.y) + (b2.y + b3.y);
    }
    for (; i < end; ++i) {
        int s0 = __ldg(csr + i);
        uint2 q0 = *reinterpret_cast<const uint2*>(feat + (size_t)s0 * DIM + co);
        float2 a0 = __half22float2(*reinterpret_cast<__half2*>(&q0.x));
        float2 b0 = __half22float2(*reinterpret_cast<__half2*>(&q0.y));
        ax += a0.x; ay += a0.y; az += b0.x; aw += b0.y;
    }
    float sc = __ldg(invdeg + v);
    reinterpret_cast<__half2*>(agg + (size_t)v * DIM)[lane * 2 + 0] = __floats2half2_rn(ax * sc, ay * sc);
    reinterpret_cast<__half2*>(agg + (size_t)v * DIM)[lane * 2 + 1] = __floats2half2_rn(az * sc, aw * sc);
}

// ------ layer-3 epilogue: out[v] = S3[v] + invdeg[v] * sum P16[s]  (fp16 gather, 64-wide) ------
__global__ void __launch_bounds__(256)
aggadd_kernel(const float* __restrict__ S, const __half* __restrict__ P,
              const int* __restrict__ rowptr, const int* __restrict__ csr,
              const float* __restrict__ invdeg, float* __restrict__ out, int n) {
    long long t = (long long)blockIdx.x * blockDim.x + threadIdx.x;
    int v = (int)(t >> 5);
    if (v >= n) return;
    int lane = (int)(t & 31);
    const int co = lane * 2;

    int beg = __ldg(rowptr + v);
    int end = __ldg(rowptr + v + 1);

    float sx = 0.f, sy = 0.f;
    int i = beg;
    for (; i + 4 <= end; i += 4) {
        int s0 = __ldg(csr + i + 0);
        int s1 = __ldg(csr + i + 1);
        int s2 = __ldg(csr + i + 2);
        int s3 = __ldg(csr + i + 3);
        float2 p0 = __half22float2(*reinterpret_cast<const __half2*>(P + (size_t)s0 * 64 + co));
        float2 p1 = __half22float2(*reinterpret_cast<const __half2*>(P + (size_t)s1 * 64 + co));
        float2 p2 = __half22float2(*reinterpret_cast<const __half2*>(P + (size_t)s2 * 64 + co));
        float2 p3 = __half22float2(*reinterpret_cast<const __half2*>(P + (size_t)s3 * 64 + co));
        sx += (p0.x + p1.x) + (p2.x + p3.x);
        sy += (p0.y + p1.y) + (p2.y + p3.y);
    }
    for (; i < end; ++i) {
        int s0 = __ldg(csr + i);
        float2 p0 = __half22float2(*reinterpret_cast<const __half2*>(P + (size_t)s0 * 64 + co));
        sx += p0.x; sy += p0.y;
    }
    float sc = __ldg(invdeg + v);
    float2 s3v = *reinterpret_cast<const float2*>(S + (size_t)v * 64 + co);
    *reinterpret_cast<float2*>(out + (size_t)v * 64 + co) =
        make_float2(s3v.x + sc * sx, s3v.y + sc * sy);
}

// ---------------- shared GEMM building blocks ----------------
__device__ __forceinline__ void load_swz(const __half* __restrict__ g, char* __restrict__ s,
                                         int rows, int t) {
    for (int i = t; i < rows * 16; i += 256) {
        int row = i >> 4, c = i & 15;
        uint4 v = *reinterpret_cast<const uint4*>(g + (size_t)row * 128 + c * 8);
        *reinterpret_cast<uint4*>(s + (size_t)row * 256 + ((c ^ (row & 7)) << 4)) = v;
    }
}
__device__ __forceinline__ void issue_1(const __half* __restrict__ a,
                                        int row0, int n, uint32_t stage, int t) {
    int valid = min(32, n - row0);
    for (int i = t; i < 512; i += 256) {
        int row = i >> 4, c = i & 15;
        uint32_t off = (uint32_t)row * 256u + (uint32_t)((c ^ (row & 7)) << 4);
        size_t goff = (size_t)(row0 + row) * 128 + c * 8;
        if (row < valid) cp16(stage + off, a + goff);
        else             zero16(stage + off);
    }
}
__device__ __forceinline__ void issue_2(const __half* __restrict__ xf, const __half* __restrict__ gf,
                                        int row0, int n, uint32_t stage, int t) {
    int valid = min(32, n - row0);
    for (int i = t; i < 512; i += 256) {
        int row = i >> 4, c = i & 15;
        uint32_t off = (uint32_t)row * 256u + (uint32_t)((c ^ (row & 7)) << 4);
        size_t goff = (size_t)(row0 + row) * 128 + c * 8;
        if (row < valid) {
            cp16(stage + off,         xf + goff);
            cp16(stage + 8192u + off, gf + goff);
        } else {
            zero16(stage + off);
            zero16(stage + 8192u + off);
        }
    }
}

// ---- fused full layer (layer 2): h = relu(X@Ws + b + AGG@Wn) -> fp16 h ----
// smem: stages 2 x 16KB (x+agg) @0/16384; weights @32768 (4 arrays x 32KB).
template <int NOUT>
__global__ void __launch_bounds__(256, 1)
gemm_kernel(const __half* __restrict__ xf, const __half* __restrict__ gf,
            const __half* __restrict__ wsh, const __half* __restrict__ wsl,
            const __half* __restrict__ wnh, const __half* __restrict__ wnl,
            const float* __restrict__ bias, __half* __restrict__ of16,
            int n, int ntiles) {
    extern __shared__ char smem[];
    constexpr int NB = NOUT * 256;
    constexpr int WBASE = 32768;
    constexpr int NPW = NOUT / 4;
    constexpr int NT = NPW / 8;
    const uint32_t sb = smem_to_u32(smem);
    const uint32_t wb = sb + WBASE;
    const int t = threadIdx.x, lane = t & 31, wid = t >> 5;

    load_swz(wsh, smem + WBASE,          NOUT, t);
    load_swz(wsl, smem + WBASE + NB,     NOUT, t);
    load_swz(wnh, smem + WBASE + 2 * NB, NOUT, t);
    load_swz(wnl, smem + WBASE + 3 * NB, NOUT, t);

    const int rhalf = (wid & 1) * 16;
    const int n0 = (wid >> 1) * NPW;
    const int arowl = rhalf + (lane & 15);
    const int akh = lane >> 4;
    const int browl = ((lane >> 4) << 3) + (lane & 7);
    const int bkh = (lane >> 3) & 1;

    float breg[NT][2];
#pragma unroll
    for (int nt = 0; nt < NT; ++nt) {
        int c = n0 + nt * 8 + (lane & 3) * 2;
        breg[nt][0] = __ldg(bias + c);
        breg[nt][1] = __ldg(bias + c + 1);
    }

    int tile = blockIdx.x, buf = 0;
    issue_2(xf, gf, tile * 32, n, sb, t);
    CP_COMMIT();

    for (; tile < ntiles; tile += gridDim.x) {
        const int nxt = tile + gridDim.x;
        if (nxt < ntiles) {
            issue_2(xf, gf, nxt * 32, n, sb + (uint32_t)(buf ^ 1) * 16384u, t);
            CP_COMMIT();
            CP_WAIT1();
        } else {
            CP_WAIT0();
        }
        __syncthreads();

        const uint32_t ab = sb + (uint32_t)buf * 16384u;
        float acc[NT][4];
#pragma unroll
        for (int q = 0; q < NT; ++q) { acc[q][0] = acc[q][1] = acc[q][2] = acc[q][3] = 0.f; }

#pragma unroll
        for (int ks = 0; ks < 8; ++ks) {
            uint32_t ac = (uint32_t)((2 * ks + akh) ^ (arowl & 7));
            uint32_t aoff = (uint32_t)arowl * 256u + (ac << 4);
            uint32_t Ax[4], Ag[4];
            ldsm_x4(Ax, ab + aoff);
            ldsm_x4(Ag, ab + 8192u + aoff);
#pragma unroll
            for (int np = 0; np < NT / 2; ++np) {
                int brow = n0 + np * 16 + browl;
                uint32_t bc = (uint32_t)((2 * ks + bkh) ^ (brow & 7));
                uint32_t boff = (uint32_t)brow * 256u + (bc << 4);
                uint32_t Bsh[4], Bsl[4], Bnh[4], Bnl[4];
                ldsm_x4(Bsh, wb + boff);
                ldsm_x4(Bsl, wb + (uint32_t)NB + boff);
                ldsm_x4(Bnh, wb + (uint32_t)(2 * NB) + boff);
                ldsm_x4(Bnl, wb + (uint32_t)(3 * NB) + boff);
                float* a0 = acc[np * 2];
                float* a1 = acc[np * 2 + 1];
                mma_f16(a0, Ax, Bsh);  mma_f16(a1, Ax, Bsh + 2);
                mma_f16(a0, Ag, Bnh);  mma_f16(a1, Ag, Bnh + 2);
                mma_f16(a0, Ax, Bsl);  mma_f16(a1, Ax, Bsl + 2);
                mma_f16(a0, Ag, Bnl);  mma_f16(a1, Ag, Bnl + 2);
            }
        }

        const int r0 = tile * 32 + rhalf + (lane >> 2);
        const int r1 = r0 + 8;
#pragma unroll
        for (int nt = 0; nt < NT; ++nt) {
            int c = n0 + nt * 8 + (lane & 3) * 2;
            float v0 = fmaxf(acc[nt][0] + breg[nt][0], 0.f);
            float v1 = fmaxf(acc[nt][1] + breg[nt][1], 0.f);
            float v2 = fmaxf(acc[nt][2] + breg[nt][0], 0.f);
            float v3 = fmaxf(acc[nt][3] + breg[nt][1], 0.f);
            if (r0 < n)
                *reinterpret_cast<__half2*>(of16 + (size_t)r0 * NOUT + c) = __floats2half2_rn(v0, v1);
            if (r1 < n)
                *reinterpret_cast<__half2*>(of16 + (size_t)r1 * NOUT + c) = __floats2half2_rn(v2, v3);
        }
        __syncthreads();
        buf ^= 1;
    }
}

// ---- half-layer GEMM. MODE 0: S = A@W + b (fp32). MODE 1: h = relu(S + A@W) -> fp16 ----
template <int NOUT, int MODE>
__global__ void __launch_bounds__(256, 1)
gemm_half_kernel(const __half* __restrict__ af, const __half* __restrict__ wh,
                 const __half* __restrict__ wl, const float* __restrict__ aux,
                 float* __restrict__ outf, __half* __restrict__ of16, int n, int ntiles) {
    extern __shared__ char smem[];
    constexpr int NB = NOUT * 256;
    constexpr int WBASE = 16384;
    constexpr int NPW = NOUT / 4;
    constexpr int NT = NPW / 8;
    const uint32_t sb = smem_to_u32(smem);
    const uint32_t wb = sb + WBASE;
    const int t = threadIdx.x, lane = t & 31, wid = t >> 5;

    load_swz(wh, smem + WBASE,      NOUT, t);
    load_swz(wl, smem + WBASE + NB, NOUT, t);

    const int rhalf = (wid & 1) * 16;
    const int n0 = (wid >> 1) * NPW;
    const int arowl = rhalf + (lane & 15);
    const int akh = lane >> 4;
    const int browl = ((lane >> 4) << 3) + (lane & 7);
    const int bkh = (lane >> 3) & 1;

    float breg[NT][2];
    if (MODE == 0) {
#pragma unroll
        for (int nt = 0; nt < NT; ++nt) {
            int c = n0 + nt * 8 + (lane & 3) * 2;
            breg[nt][0] = __ldg(aux + c);
            breg[nt][1] = __ldg(aux + c + 1);
        }
    }

    int tile = blockIdx.x, buf = 0;
    issue_1(af, tile * 32, n, sb, t);
    CP_COMMIT();

    for (; tile < ntiles; tile += gridDim.x) {
        const int nxt = tile + gridDim.x;
        if (nxt < ntiles) {
            issue_1(af, nxt * 32, n, sb + (uint32_t)(buf ^ 1) * 8192u, t);
            CP_COMMIT();
            CP_WAIT1();
        } else {
            CP_WAIT0();
        }
        __syncthreads();

        const uint32_t ab = sb + (uint32_t)buf * 8192u;
        float acc[NT][4];
#pragma unroll
        for (int q = 0; q < NT; ++q) { acc[q][0] = acc[q][1] = acc[q][2] = acc[q][3] = 0.f; }

#pragma unroll
        for (int ks = 0; ks < 8; ++ks) {
            uint32_t ac = (uint32_t)((2 * ks + akh) ^ (arowl & 7));
            uint32_t aoff = (uint32_t)arowl * 256u + (ac << 4);
            uint32_t A[4];
            ldsm_x4(A, ab + aoff);
#pragma unroll
            for (int np = 0; np < NT / 2; ++np) {
                int brow = n0 + np * 16 + browl;
                uint32_t bc = (uint32_t)((2 * ks + bkh) ^ (brow & 7));
                uint32_t boff = (uint32_t)brow * 256u + (bc << 4);
                uint32_t Bh[4], Bl[4];
                ldsm_x4(Bh, wb + boff);
                ldsm_x4(Bl, wb + (uint32_t)NB + boff);
                float* a0 = acc[np * 2];
                float* a1 = acc[np * 2 + 1];
                mma_f16(a0, A, Bh);  mma_f16(a1, A, Bh + 2);
                mma_f16(a0, A, Bl);  mma_f16(a1, A, Bl + 2);
            }
        }

        const int r0 = tile * 32 + rhalf + (lane >> 2);
        const int r1 = r0 + 8;
#pragma unroll
        for (int nt = 0; nt < NT; ++nt) {
            int c = n0 + nt * 8 + (lane & 3) * 2;
            float v0 = acc[nt][0], v1 = acc[nt][1], v2 = acc[nt][2], v3 = acc[nt][3];
            if (MODE == 0) {
                v0 += breg[nt][0]; v1 += breg[nt][1];
                v2 += breg[nt][0]; v3 += breg[nt][1];
                if (r0 < n)
                    *reinterpret_cast<float2*>(outf + (size_t)r0 * NOUT + c) = make_float2(v0, v1);
                if (r1 < n)
                    *reinterpret_cast<float2*>(outf + (size_t)r1 * NOUT + c) = make_float2(v2, v3);
            } else {
                if (r0 < n) {
                    float2 s = *reinterpret_cast<const float2*>(aux + (size_t)r0 * NOUT + c);
                    v0 = fmaxf(v0 + s.x, 0.f); v1 = fmaxf(v1 + s.y, 0.f);
                    *reinterpret_cast<__half2*>(of16 + (size_t)r0 * NOUT + c) = __floats2half2_rn(v0, v1);
                }
                if (r1 < n) {
                    float2 s = *reinterpret_cast<const float2*>(aux + (size_t)r1 * NOUT + c);
                    v2 = fmaxf(v2 + s.x, 0.f); v3 = fmaxf(v3 + s.y, 0.f);
                    *reinterpret_cast<__half2*>(of16 + (size_t)r1 * NOUT + c) = __floats2half2_rn(v2, v3);
                }
            }
        }
        __syncthreads();
        buf ^= 1;
    }
}

// ---- layer-3 dual GEMM: S = X@Ws + b (fp32), P = X@Wn (fp16), A tiles loaded once ----
__global__ void __launch_bounds__(256, 1)
gemm3_dual_kernel(const __half* __restrict__ xf,
                  const __half* __restrict__ wsh, const __half* __restrict__ wsl,
                  const __half* __restrict__ wnh, const __half* __restrict__ wnl,
                  const float* __restrict__ bias, float* __restrict__ S,
                  __half* __restrict__ P, int n, int ntiles) {
    extern __shared__ char smem[];
    constexpr int NB = 64 * 256;
    constexpr int WBASE = 16384;
    const uint32_t sb = smem_to_u32(smem);
    const uint32_t wb = sb + WBASE;
    const int t = threadIdx.x, lane = t & 31, wid = t >> 5;

    load_swz(wsh, smem + WBASE,          64, t);
    load_swz(wsl, smem + WBASE + NB,     64, t);
    load_swz(wnh, smem + WBASE + 2 * NB, 64, t);
    load_swz(wnl, smem + WBASE + 3 * NB, 64, t);

    const int rhalf = (wid & 1) * 16;
    const int n0 = (wid >> 1) * 16;
    const int arowl = rhalf + (lane & 15);
    const int akh = lane >> 4;
    const int browl = ((lane >> 4) << 3) + (lane & 7);
    const int bkh = (lane >> 3) & 1;
    const int brow = n0 + browl;

    float breg[2][2];
#pragma unroll
    for (int nt = 0; nt < 2; ++nt) {
        int c = n0 + nt * 8 + (lane & 3) * 2;
        breg[nt][0] = __ldg(bias + c);
        breg[nt][1] = __ldg(bias + c + 1);
    }

    int tile = blockIdx.x, buf = 0;
    issue_1(xf, tile * 32, n, sb, t);
    CP_COMMIT();

    for (; tile < ntiles; tile += gridDim.x) {
        const int nxt = tile + gridDim.x;
        if (nxt < ntiles) {
            issue_1(xf, nxt * 32, n, sb + (uint32_t)(buf ^ 1) * 8192u, t);
            CP_COMMIT();
            CP_WAIT1();
        } else {
            CP_WAIT0();
        }
        __syncthreads();

        const uint32_t ab = sb + (uint32_t)buf * 8192u;
        float accS[2][4], accP[2][4];
#pragma unroll
        for (int q = 0; q < 2; ++q) {
            accS[q][0] = accS[q][1] = accS[q][2] = accS[q][3] = 0.f;
            accP[q][0] = accP[q][1] = accP[q][2] = accP[q][3] = 0.f;
        }

#pragma unroll
        for (int ks = 0; ks < 8; ++ks) {
            uint32_t ac = (uint32_t)((2 * ks + akh) ^ (arowl & 7));
            uint32_t aoff = (uint32_t)arowl * 256u + (ac << 4);
            uint32_t A[4];
            ldsm_x4(A, ab + aoff);
            uint32_t bc = (uint32_t)((2 * ks + bkh) ^ (brow & 7));
            uint32_t boff = (uint32_t)brow * 256u + (bc << 4);
            uint32_t Bsh[4], Bsl[4], Bnh[4], Bnl[4];
            ldsm_x4(Bsh, wb + boff);
            ldsm_x4(Bsl, wb + (uint32_t)NB + boff);
            ldsm_x4(Bnh, wb + (uint32_t)(2 * NB) + boff);
            ldsm_x4(Bnl, wb + (uint32_t)(3 * NB) + boff);
            mma_f16(accS[0], A, Bsh);  mma_f16(accS[1], A, Bsh + 2);
            mma_f16(accP[0], A, Bnh);  mma_f16(accP[1], A, Bnh + 2);
            mma_f16(accS[0], A, Bsl);  mma_f16(accS[1], A, Bsl + 2);
            mma_f16(accP[0], A, Bnl);  mma_f16(accP[1], A, Bnl + 2);
        }

        const int r0 = tile * 32 + rhalf + (lane >> 2);
        const int r1 = r0 + 8;
#pragma unroll
        for (int nt = 0; nt < 2; ++nt) {
            int c = n0 + nt * 8 + (lane & 3) * 2;
            if (r0 < n) {
                *reinterpret_cast<float2*>(S + (size_t)r0 * 64 + c) =
                    make_float2(accS[nt][0] + breg[nt][0], accS[nt][1] + breg[nt][1]);
                *reinterpret_cast<__half2*>(P + (size_t)r0 * 64 + c) =
                    __floats2half2_rn(accP[nt][0], accP[nt][1]);
            }
            if (r1 < n) {
                *reinterpret_cast<float2*>(S + (size_t)r1 * 64 + c) =
                    make_float2(accS[nt][2] + breg[nt][0], accS[nt][3] + breg[nt][1]);
                *reinterpret_cast<__half2*>(P + (size_t)r1 * 64 + c) =
                    __floats2half2_rn(accP[nt][2], accP[nt][3]);
            }
        }
        __syncthreads();
        buf ^= 1;
    }
}

// ---------------- launch ----------------
extern "C" void kernel_launch(void* const* d_in, const int* in_sizes, int n_in,
                              void* d_out, int out_size) {
    const float* x   = (const float*)d_in[0];
    const int*   src = (const int*)d_in[1];
    const int*   dst = (const int*)d_in[2];
    const float* Ws1 = (const float*)d_in[3];
    const float* b1  = (const float*)d_in[4];
    const float* Wn1 = (const float*)d_in[5];
    const float* Ws2 = (const float*)d_in[6];
    const float* b2  = (const float*)d_in[7];
    const float* Wn2 = (const float*)d_in[8];
    const float* Ws3 = (const float*)d_in[9];
    const float* b3  = (const float*)d_in[10];
    const float* Wn3 = (const float*)d_in[11];

    const int N = in_sizes[0] / DIM;
    const int E = in_sizes[1];
    float* out = (float*)d_out;

    int *deg_i, *rowptr, *csr;
    float *invdeg, *S1, *S3;
    __half *P16, *xf16, *hf16, *agg16, *wth, *wtl;
    cudaGetSymbolAddress((void**)&deg_i,  g_deg_i);
    cudaGetSymbolAddress((void**)&rowptr, g_rowptr);
    cudaGetSymbolAddress((void**)&csr,    g_csr);
    cudaGetSymbolAddress((void**)&invdeg, g_invdeg);
    cudaGetSymbolAddress((void**)&S1,     g_S1);
    cudaGetSymbolAddress((void**)&S3,     g_S3);
    cudaGetSymbolAddress((void**)&P16,    g_P16);
    cudaGetSymbolAddress((void**)&xf16,   g_xf16);
    cudaGetSymbolAddress((void**)&hf16,   g_hf16);
    cudaGetSymbolAddress((void**)&agg16,  g_agg16);
    cudaGetSymbolAddress((void**)&wth,    g_wth);
    cudaGetSymbolAddress((void**)&wtl,    g_wtl);

    // one-time host-side setup (runs on the non-captured correctness call first)
    static cudaStream_t s1 = nullptr;
    static cudaEvent_t evf, evsp, ea1;
    if (!s1) {
        cudaStreamCreateWithFlags(&s1, cudaStreamNonBlocking);
        cudaEventCreateWithFlags(&evf,  cudaEventDisableTiming);
        cudaEventCreateWithFlags(&evsp, cudaEventDisableTiming);
        cudaEventCreateWithFlags(&ea1,  cudaEventDisableTiming);
    }

    const int SMF = 32768 + 4 * 128 * 256;   // 163840 (fused layer 2)
    const int SMH = 16384 + 2 * 128 * 256;   // 81920  (half GEMMs)
    const int SM3 = 16384 + 4 * 64 * 256;    // 81920  (layer-3 dual)
    cudaFuncSetAttribute(gemm_kernel<128>,
                         cudaFuncAttributeMaxDynamicSharedMemorySize, SMF);
    cudaFuncSetAttribute(gemm_half_kernel<128, 0>,
                         cudaFuncAttributeMaxDynamicSharedMemorySize, SMH);
    cudaFuncSetAttribute(gemm_half_kernel<128, 1>,
                         cudaFuncAttributeMaxDynamicSharedMemorySize, SMH);
    cudaFuncSetAttribute(gemm3_dual_kernel,
                         cudaFuncAttributeMaxDynamicSharedMemorySize, SM3);

    const int nb_edges = (E + 255) / 256;
    const int nb_agg   = (int)(((long long)N * 32 + 255) / 256);
    const int ntiles   = (N + 31) / 32;
    const int GRID     = 152;

    // ---- fork: s1 builds CSR while s0 does conversions; agg1 (s1) waits on the convert ----
    cudaEventRecord(evf, 0);
    cudaStreamWaitEvent(s1, evf, 0);

    // deg_i is all-zero at entry (zero-init + fill_csr countdown restores it)
    deg_kernel<<<nb_edges, 256, 0, s1>>>(dst, deg_i, E);
    scan_kernel<<<1, 1024, 0, s1>>>(deg_i, rowptr, invdeg, N);
    fill_csr_kernel<<<nb_edges, 256, 0, s1>>>(src, dst, rowptr, deg_i, csr, E);

    split_kernel<<<(N * DIM / 2 + 255) / 256, 256>>>(x, xf16, N * DIM / 2);
    cudaEventRecord(evsp, 0);
    wsplit_kernel<<<(81920 + 255) / 256, 256>>>(Ws1, Wn1, Ws2, Wn2, Ws3, Wn3, wth, wtl);

    cudaStreamWaitEvent(s1, evsp, 0);
    agg_kernel<<<nb_agg, 256, 0, s1>>>(xf16, rowptr, csr, invdeg, agg16, N);
    cudaEventRecord(ea1, s1);

    // s0: layer-1 self GEMM overlaps with CSR + agg1
    gemm_half_kernel<128, 0><<<GRID, 256, SMH>>>(
        xf16, wth + 0 * 16384, wtl + 0 * 16384, b1, S1, nullptr, N, ntiles);

    // ---- join: layer-1 neigh + the rest run single-stream ----
    cudaStreamWaitEvent(0, ea1, 0);
    gemm_half_kernel<128, 1><<<GRID, 256, SMH>>>(
        agg16, wth + 1 * 16384, wtl + 1 * 16384, S1, nullptr, hf16, N, ntiles);

    // Layer 2 (fused)
    agg_kernel<<<nb_agg, 256>>>(hf16, rowptr, csr, invdeg, agg16, N);
    gemm_kernel<128><<<GRID, 256, SMF>>>(
        hf16, agg16,
        wth + 2 * 16384, wtl + 2 * 16384, wth + 3 * 16384, wtl + 3 * 16384,
        b2, hf16, N, ntiles);

    // Layer 3: lin-before-mp (matches reference)
    gemm3_dual_kernel<<<GRID, 256, SM3>>>(
        hf16,
        wth + 4 * 16384, wtl + 4 * 16384, wth + 5 * 16384, wtl + 5 * 16384,
        b3, S3, P16, N, ntiles);
    aggadd_kernel<<<nb_agg, 256>>>(S3, P16, rowptr, csr, invdeg, out, N);
}

// round 16
// speedup vs baseline: 1.1066x; 1.0267x over previous
#include <cuda_runtime.h>
#include <cuda_fp16.h>
#include <cstdint>

#define DIM 128
#define NODES_MAX 50048
#define EDGES_MAX 800000

// ---------------- device scratch (allocation-free rule) ----------------
// g_deg_i is zero at every kernel_launch entry: zero-initialized at load, and
// fill_csr_kernel's atomic countdown restores it to exactly zero each run.
__device__ int   g_deg_i[NODES_MAX];
__device__ int   g_rowptr[NODES_MAX + 1];
__device__ int   g_csr[EDGES_MAX];
__device__ float g_invdeg[NODES_MAX];
__device__ __align__(16) float  g_S1[(size_t)NODES_MAX * DIM];  // layer-1 self partial (fp32)
__device__ __align__(16) float  g_S3[(size_t)NODES_MAX * 64];   // layer-3 self partial (fp32)
__device__ __align__(16) __half g_P16[(size_t)NODES_MAX * 64];  // layer-3 h@Wn3 (fp16)
__device__ __align__(16) __half g_xf16[(size_t)NODES_MAX * DIM];// fp16 activations
__device__ __align__(16) __half g_hf16[(size_t)NODES_MAX * DIM];
__device__ __align__(16) __half g_agg16[(size_t)NODES_MAX * DIM];
__device__ __align__(16) __half g_wth[6 * 16384];               // transposed [N][K] weight hi (fp16)
__device__ __align__(16) __half g_wtl[6 * 16384];               // lo parts (fp16)

// ---------------- PTX helpers (sm_80-baseline features only) ----------------
__device__ __forceinline__ uint32_t smem_to_u32(const void* p) {
    uint32_t a;
    asm("{ .reg .u64 t; cvta.to.shared.u64 t, %1; cvt.u32.u64 %0, t; }" : "=r"(a) : "l"(p));
    return a;
}
__device__ __forceinline__ void ldsm_x4(uint32_t* r, uint32_t addr) {
    asm volatile("ldmatrix.sync.aligned.m8n8.x4.shared.b16 {%0,%1,%2,%3}, [%4];"
                 : "=r"(r[0]), "=r"(r[1]), "=r"(r[2]), "=r"(r[3]) : "r"(addr));
}
__device__ __forceinline__ void mma_f16(float* d, const uint32_t* a, const uint32_t* b) {
    asm volatile(
        "mma.sync.aligned.m16n8k16.row.col.f32.f16.f16.f32 "
        "{%0,%1,%2,%3}, {%4,%5,%6,%7}, {%8,%9}, {%0,%1,%2,%3};"
        : "+f"(d[0]), "+f"(d[1]), "+f"(d[2]), "+f"(d[3])
        : "r"(a[0]), "r"(a[1]), "r"(a[2]), "r"(a[3]), "r"(b[0]), "r"(b[1]));
}
__device__ __forceinline__ void cp16(uint32_t d, const void* g) {
    asm volatile("cp.async.cg.shared.global [%0], [%1], 16;" :: "r"(d), "l"(g));
}
__device__ __forceinline__ void zero16(uint32_t d) {
    asm volatile("st.shared.v4.b32 [%0], {%1,%1,%1,%1};" :: "r"(d), "r"(0u));
}
#define CP_COMMIT() asm volatile("cp.async.commit_group;" ::: "memory")
#define CP_WAIT1()  asm volatile("cp.async.wait_group 1;" ::: "memory")
#define CP_WAIT0()  asm volatile("cp.async.wait_group 0;" ::: "memory")

// ---------------- CSR build ----------------
__global__ void deg_kernel(const int* __restrict__ dst, int* __restrict__ deg, int E) {
    int e = blockIdx.x * blockDim.x + threadIdx.x;
    if (e < E) atomicAdd(&deg[dst[e]], 1);
}
__global__ void __launch_bounds__(1024)
scan_kernel(const int* __restrict__ cnt, int* __restrict__ rowptr,
            float* __restrict__ inv, int n) {
    __shared__ int wsum[32];
    const int tid = threadIdx.x;
    const int CH = (n + 1023) / 1024;
    const int base = tid * CH;
    int s = 0;
    for (int j = 0; j < CH; ++j) { int i = base + j; if (i < n) s += __ldg(cnt + i); }
    int v = s;
#pragma unroll
    for (int o = 1; o < 32; o <<= 1) { int u = __shfl_up_sync(~0u, v, o); if ((tid & 31) >= o) v += u; }
    if ((tid & 31) == 31) wsum[tid >> 5] = v;
    __syncthreads();
    if (tid < 32) {
        int w = wsum[tid];
#pragma unroll
        for (int o = 1; o < 32; o <<= 1) { int u = __shfl_up_sync(~0u, w, o); if (tid >= o) w += u; }
        wsum[tid] = w;
    }
    __syncthreads();
    int run = (v - s) + ((tid >= 32) ? wsum[(tid >> 5) - 1] : 0);
    for (int j = 0; j < CH; ++j) {
        int i = base + j;
        if (i < n) {
            int c = __ldg(cnt + i);
            run += c;
            rowptr[i + 1] = run;
            inv[i] = 1.0f / (float)max(c, 1);
        }
    }
    if (tid == 0) rowptr[0] = 0;
}
// fill via atomic countdown on deg (restores deg to all-zero for the next replay)
__global__ void fill_csr_kernel(const int* __restrict__ src, const int* __restrict__ dst,
                                const int* __restrict__ rowptr, int* __restrict__ deg,
                                int* __restrict__ csr, int E) {
    int e = blockIdx.x * blockDim.x + threadIdx.x;
    if (e < E) {
        int d = dst[e];
        int cnt = atomicAdd(&deg[d], -1);
        csr[rowptr[d] + cnt - 1] = src[e];
    }
}

// ---------------- fused conversions: x -> fp16, all weights -> transposed fp16 hi/lo ----------------
__global__ void convert_kernel(const float* __restrict__ x, __half* __restrict__ f16, int n2,
                               const float* W1s, const float* W1n, const float* W2s,
                               const float* W2n, const float* W3s, const float* W3n,
                               __half* __restrict__ th, __half* __restrict__ tl) {
    int i = blockIdx.x * blockDim.x + threadIdx.x;
    if (i < n2) {
        float2 v = reinterpret_cast<const float2*>(x)[i];
        reinterpret_cast<__half2*>(f16)[i] = __floats2half2_rn(v.x, v.y);
        return;
    }
    int j = i - n2;
    int m, off;
    if (j < 4 * 16384) { m = j / 16384; off = j % 16384; }
    else {
        int k = j - 4 * 16384;
        if (k >= 2 * 8192) return;
        m = 4 + k / 8192; off = k % 8192;
    }
    const float* src = (m == 0) ? W1s : (m == 1) ? W1n : (m == 2) ? W2s
                     : (m == 3) ? W2n : (m == 4) ? W3s : W3n;
    int Ncols = (m < 4) ? 128 : 64;
    int nn = off / 128, kk = off % 128;
    float v = src[kk * Ncols + nn];
    __half h = __float2half(v);
    th[m * 16384 + off] = h;
    tl[m * 16384 + off] = __float2half(v - __half2float(h));
}

// -------- atomic-free mean aggregation (fp16 gather, fp32 accumulate, fp16 out; MLP=16) --------
__global__ void __launch_bounds__(256)
agg_kernel(const __half* __restrict__ feat, const int* __restrict__ rowptr,
           const int* __restrict__ csr, const float* __restrict__ invdeg,
           __half* __restrict__ agg, int n) {
    long long t = (long long)blockIdx.x * blockDim.x + threadIdx.x;
    int v = (int)(t >> 5);
    if (v >= n) return;
    int lane = (int)(t & 31);
    const int co = lane * 4;

    int beg = __ldg(rowptr + v);
    int end = __ldg(rowptr + v + 1);

    float ax = 0.f, ay = 0.f, az = 0.f, aw = 0.f;
    int i = beg;
    for (; i + 8 <= end; i += 8) {
        uint2 q[8];
#pragma unroll
        for (int u = 0; u < 8; ++u) {
            int s = __ldg(csr + i + u);
            q[u] = *reinterpret_cast<const uint2*>(feat + (size_t)s * DIM + co);
        }
#pragma unroll
        for (int u = 0; u < 8; ++u) {
            float2 a = __half22float2(*reinterpret_cast<__half2*>(&q[u].x));
            float2 b = __half22float2(*reinterpret_cast<__half2*>(&q[u].y));
            ax += a.x; ay += a.y; az += b.x; aw += b.y;
        }
    }
    for (; i < end; ++i) {
        int s0 = __ldg(csr + i);
        uint2 q0 = *reinterpret_cast<const uint2*>(feat + (size_t)s0 * DIM + co);
        float2 a0 = __half22float2(*reinterpret_cast<__half2*>(&q0.x));
        float2 b0 = __half22float2(*reinterpret_cast<__half2*>(&q0.y));
        ax += a0.x; ay += a0.y; az += b0.x; aw += b0.y;
    }
    float sc = __ldg(invdeg + v);
    reinterpret_cast<__half2*>(agg + (size_t)v * DIM)[lane * 2 + 0] = __floats2half2_rn(ax * sc, ay * sc);
    reinterpret_cast<__half2*>(agg + (size_t)v * DIM)[lane * 2 + 1] = __floats2half2_rn(az * sc, aw * sc);
}

// ------ layer-3 epilogue: out[v] = S3[v] + invdeg[v] * sum P16[s]; 2 nodes/warp, 16 lanes each ------
__global__ void __launch_bounds__(256)
aggadd_kernel(const float* __restrict__ S, const __half* __restrict__ P,
              const int* __restrict__ rowptr, const int* __restrict__ csr,
              const float* __restrict__ invdeg, float* __restrict__ out, int n) {
    long long t = (long long)blockIdx.x * blockDim.x + threadIdx.x;
    int v = (int)(t >> 4);              // 16 lanes per node
    if (v >= n) return;
    int sl = (int)(t & 15);
    const int co = sl * 4;              // 4 fp16 cols per sub-lane (8B)

    int beg = __ldg(rowptr + v);
    int end = __ldg(rowptr + v + 1);

    float sx = 0.f, sy = 0.f, sz = 0.f, sw = 0.f;
    int i = beg;
    for (; i + 4 <= end; i += 4) {
        uint2 q[4];
#pragma unroll
        for (int u = 0; u < 4; ++u) {
            int s = __ldg(csr + i + u);
            q[u] = *reinterpret_cast<const uint2*>(P + (size_t)s * 64 + co);
        }
#pragma unroll
        for (int u = 0; u < 4; ++u) {
            float2 a = __half22float2(*reinterpret_cast<__half2*>(&q[u].x));
            float2 b = __half22float2(*reinterpret_cast<__half2*>(&q[u].y));
            sx += a.x; sy += a.y; sz += b.x; sw += b.y;
        }
    }
    for (; i < end; ++i) {
        int s0 = __ldg(csr + i);
        uint2 q0 = *reinterpret_cast<const uint2*>(P + (size_t)s0 * 64 + co);
        float2 a0 = __half22float2(*reinterpret_cast<__half2*>(&q0.x));
        float2 b0 = __half22float2(*reinterpret_cast<__half2*>(&q0.y));
        sx += a0.x; sy += a0.y; sz += b0.x; sw += b0.y;
    }
    float sc = __ldg(invdeg + v);
    float4 s3v = *reinterpret_cast<const float4*>(S + (size_t)v * 64 + co);
    *reinterpret_cast<float4*>(out + (size_t)v * 64 + co) =
        make_float4(s3v.x + sc * sx, s3v.y + sc * sy, s3v.z + sc * sz, s3v.w + sc * sw);
}

// ---------------- shared GEMM building blocks ----------------
__device__ __forceinline__ void load_swz(const __half* __restrict__ g, char* __restrict__ s,
                                         int rows, int t) {
    for (int i = t; i < rows * 16; i += 256) {
        int row = i >> 4, c = i & 15;
        uint4 v = *reinterpret_cast<const uint4*>(g + (size_t)row * 128 + c * 8);
        *reinterpret_cast<uint4*>(s + (size_t)row * 256 + ((c ^ (row & 7)) << 4)) = v;
    }
}
__device__ __forceinline__ void issue_1(const __half* __restrict__ a,
                                        int row0, int n, uint32_t stage, int t) {
    int valid = min(32, n - row0);
    for (int i = t; i < 512; i += 256) {
        int row = i >> 4, c = i & 15;
        uint32_t off = (uint32_t)row * 256u + (uint32_t)((c ^ (row & 7)) << 4);
        size_t goff = (size_t)(row0 + row) * 128 + c * 8;
        if (row < valid) cp16(stage + off, a + goff);
        else             zero16(stage + off);
    }
}
__device__ __forceinline__ void issue_2(const __half* __restrict__ xf, const __half* __restrict__ gf,
                                        int row0, int n, uint32_t stage, int t) {
    int valid = min(32, n - row0);
    for (int i = t; i < 512; i += 256) {
        int row = i >> 4, c = i & 15;
        uint32_t off = (uint32_t)row * 256u + (uint32_t)((c ^ (row & 7)) << 4);
        size_t goff = (size_t)(row0 + row) * 128 + c * 8;
        if (row < valid) {
            cp16(stage + off,         xf + goff);
            cp16(stage + 8192u + off, gf + goff);
        } else {
            zero16(stage + off);
            zero16(stage + 8192u + off);
        }
    }
}

// ---- fused full layer (layer 2): h = relu(X@Ws + b + AGG@Wn) -> fp16 h ----
template <int NOUT>
__global__ void __launch_bounds__(256, 1)
gemm_kernel(const __half* __restrict__ xf, const __half* __restrict__ gf,
            const __half* __restrict__ wsh, const __half* __restrict__ wsl,
            const __half* __restrict__ wnh, const __half* __restrict__ wnl,
            const float* __restrict__ bias, __half* __restrict__ of16,
            int n, int ntiles) {
    extern __shared__ char smem[];
    constexpr int NB = NOUT * 256;
    constexpr int WBASE = 32768;
    constexpr int NPW = NOUT / 4;
    constexpr int NT = NPW / 8;
    const uint32_t sb = smem_to_u32(smem);
    const uint32_t wb = sb + WBASE;
    const int t = threadIdx.x, lane = t & 31, wid = t >> 5;

    load_swz(wsh, smem + WBASE,          NOUT, t);
    load_swz(wsl, smem + WBASE + NB,     NOUT, t);
    load_swz(wnh, smem + WBASE + 2 * NB, NOUT, t);
    load_swz(wnl, smem + WBASE + 3 * NB, NOUT, t);

    const int rhalf = (wid & 1) * 16;
    const int n0 = (wid >> 1) * NPW;
    const int arowl = rhalf + (lane & 15);
    const int akh = lane >> 4;
    const int browl = ((lane >> 4) << 3) + (lane & 7);
    const int bkh = (lane >> 3) & 1;

    float breg[NT][2];
#pragma unroll
    for (int nt = 0; nt < NT; ++nt) {
        int c = n0 + nt * 8 + (lane & 3) * 2;
        breg[nt][0] = __ldg(bias + c);
        breg[nt][1] = __ldg(bias + c + 1);
    }

    int tile = blockIdx.x, buf = 0;
    issue_2(xf, gf, tile * 32, n, sb, t);
    CP_COMMIT();

    for (; tile < ntiles; tile += gridDim.x) {
        const int nxt = tile + gridDim.x;
        if (nxt < ntiles) {
            issue_2(xf, gf, nxt * 32, n, sb + (uint32_t)(buf ^ 1) * 16384u, t);
            CP_COMMIT();
            CP_WAIT1();
        } else {
            CP_WAIT0();
        }
        __syncthreads();

        const uint32_t ab = sb + (uint32_t)buf * 16384u;
        float acc[NT][4];
#pragma unroll
        for (int q = 0; q < NT; ++q) { acc[q][0] = acc[q][1] = acc[q][2] = acc[q][3] = 0.f; }

#pragma unroll
        for (int ks = 0; ks < 8; ++ks) {
            uint32_t ac = (uint32_t)((2 * ks + akh) ^ (arowl & 7));
            uint32_t aoff = (uint32_t)arowl * 256u + (ac << 4);
            uint32_t Ax[4], Ag[4];
            ldsm_x4(Ax, ab + aoff);
            ldsm_x4(Ag, ab + 8192u + aoff);
#pragma unroll
            for (int np = 0; np < NT / 2; ++np) {
                int brow = n0 + np * 16 + browl;
                uint32_t bc = (uint32_t)((2 * ks + bkh) ^ (brow & 7));
                uint32_t boff = (uint32_t)brow * 256u + (bc << 4);
                uint32_t Bsh[4], Bsl[4], Bnh[4], Bnl[4];
                ldsm_x4(Bsh, wb + boff);
                ldsm_x4(Bsl, wb + (uint32_t)NB + boff);
                ldsm_x4(Bnh, wb + (uint32_t)(2 * NB) + boff);
                ldsm_x4(Bnl, wb + (uint32_t)(3 * NB) + boff);
                float* a0 = acc[np * 2];
                float* a1 = acc[np * 2 + 1];
                mma_f16(a0, Ax, Bsh);  mma_f16(a1, Ax, Bsh + 2);
                mma_f16(a0, Ag, Bnh);  mma_f16(a1, Ag, Bnh + 2);
                mma_f16(a0, Ax, Bsl);  mma_f16(a1, Ax, Bsl + 2);
                mma_f16(a0, Ag, Bnl);  mma_f16(a1, Ag, Bnl + 2);
            }
        }

        const int r0 = tile * 32 + rhalf + (lane >> 2);
        const int r1 = r0 + 8;
#pragma unroll
        for (int nt = 0; nt < NT; ++nt) {
            int c = n0 + nt * 8 + (lane & 3) * 2;
            float v0 = fmaxf(acc[nt][0] + breg[nt][0], 0.f);
            float v1 = fmaxf(acc[nt][1] + breg[nt][1], 0.f);
            float v2 = fmaxf(acc[nt][2] + breg[nt][0], 0.f);
            float v3 = fmaxf(acc[nt][3] + breg[nt][1], 0.f);
            if (r0 < n)
                *reinterpret_cast<__half2*>(of16 + (size_t)r0 * NOUT + c) = __floats2half2_rn(v0, v1);
            if (r1 < n)
                *reinterpret_cast<__half2*>(of16 + (size_t)r1 * NOUT + c) = __floats2half2_rn(v2, v3);
        }
        __syncthreads();
        buf ^= 1;
    }
}

// ---- half-layer GEMM. MODE 0: S = A@W + b (fp32). MODE 1: h = relu(S + A@W) -> fp16 ----
template <int NOUT, int MODE>
__global__ void __launch_bounds__(256, 1)
gemm_half_kernel(const __half* __restrict__ af, const __half* __restrict__ wh,
                 const __half* __restrict__ wl, const float* __restrict__ aux,
                 float* __restrict__ outf, __half* __restrict__ of16, int n, int ntiles) {
    extern __shared__ char smem[];
    constexpr int NB = NOUT * 256;
    constexpr int WBASE = 16384;
    constexpr int NPW = NOUT / 4;
    constexpr int NT = NPW / 8;
    const uint32_t sb = smem_to_u32(smem);
    const uint32_t wb = sb + WBASE;
    const int t = threadIdx.x, lane = t & 31, wid = t >> 5;

    load_swz(wh, smem + WBASE,      NOUT, t);
    load_swz(wl, smem + WBASE + NB, NOUT, t);

    const int rhalf = (wid & 1) * 16;
    const int n0 = (wid >> 1) * NPW;
    const int arowl = rhalf + (lane & 15);
    const int akh = lane >> 4;
    const int browl = ((lane >> 4) << 3) + (lane & 7);
    const int bkh = (lane >> 3) & 1;

    float breg[NT][2];
    if (MODE == 0) {
#pragma unroll
        for (int nt = 0; nt < NT; ++nt) {
            int c = n0 + nt * 8 + (lane & 3) * 2;
            breg[nt][0] = __ldg(aux + c);
            breg[nt][1] = __ldg(aux + c + 1);
        }
    }

    int tile = blockIdx.x, buf = 0;
    issue_1(af, tile * 32, n, sb, t);
    CP_COMMIT();

    for (; tile < ntiles; tile += gridDim.x) {
        const int nxt = tile + gridDim.x;
        if (nxt < ntiles) {
            issue_1(af, nxt * 32, n, sb + (uint32_t)(buf ^ 1) * 8192u, t);
            CP_COMMIT();
            CP_WAIT1();
        } else {
            CP_WAIT0();
        }
        __syncthreads();

        const uint32_t ab = sb + (uint32_t)buf * 8192u;
        float acc[NT][4];
#pragma unroll
        for (int q = 0; q < NT; ++q) { acc[q][0] = acc[q][1] = acc[q][2] = acc[q][3] = 0.f; }

#pragma unroll
        for (int ks = 0; ks < 8; ++ks) {
            uint32_t ac = (uint32_t)((2 * ks + akh) ^ (arowl & 7));
            uint32_t aoff = (uint32_t)arowl * 256u + (ac << 4);
            uint32_t A[4];
            ldsm_x4(A, ab + aoff);
#pragma unroll
            for (int np = 0; np < NT / 2; ++np) {
                int brow = n0 + np * 16 + browl;
                uint32_t bc = (uint32_t)((2 * ks + bkh) ^ (brow & 7));
                uint32_t boff = (uint32_t)brow * 256u + (bc << 4);
                uint32_t Bh[4], Bl[4];
                ldsm_x4(Bh, wb + boff);
                ldsm_x4(Bl, wb + (uint32_t)NB + boff);
                float* a0 = acc[np * 2];
                float* a1 = acc[np * 2 + 1];
                mma_f16(a0, A, Bh);  mma_f16(a1, A, Bh + 2);
                mma_f16(a0, A, Bl);  mma_f16(a1, A, Bl + 2);
            }
        }

        const int r0 = tile * 32 + rhalf + (lane >> 2);
        const int r1 = r0 + 8;
#pragma unroll
        for (int nt = 0; nt < NT; ++nt) {
            int c = n0 + nt * 8 + (lane & 3) * 2;
            float v0 = acc[nt][0], v1 = acc[nt][1], v2 = acc[nt][2], v3 = acc[nt][3];
            if (MODE == 0) {
                v0 += breg[nt][0]; v1 += breg[nt][1];
                v2 += breg[nt][0]; v3 += breg[nt][1];
                if (r0 < n)
                    *reinterpret_cast<float2*>(outf + (size_t)r0 * NOUT + c) = make_float2(v0, v1);
                if (r1 < n)
                    *reinterpret_cast<float2*>(outf + (size_t)r1 * NOUT + c) = make_float2(v2, v3);
            } else {
                if (r0 < n) {
                    float2 s = *reinterpret_cast<const float2*>(aux + (size_t)r0 * NOUT + c);
                    v0 = fmaxf(v0 + s.x, 0.f); v1 = fmaxf(v1 + s.y, 0.f);
                    *reinterpret_cast<__half2*>(of16 + (size_t)r0 * NOUT + c) = __floats2half2_rn(v0, v1);
                }
                if (r1 < n) {
                    float2 s = *reinterpret_cast<const float2*>(aux + (size_t)r1 * NOUT + c);
                    v2 = fmaxf(v2 + s.x, 0.f); v3 = fmaxf(v3 + s.y, 0.f);
                    *reinterpret_cast<__half2*>(of16 + (size_t)r1 * NOUT + c) = __floats2half2_rn(v2, v3);
                }
            }
        }
        __syncthreads();
        buf ^= 1;
    }
}

// ---- layer-3 dual GEMM: S = X@Ws + b (fp32), P = X@Wn (fp16), A tiles loaded once ----
__global__ void __launch_bounds__(256, 1)
gemm3_dual_kernel(const __half* __restrict__ xf,
                  const __half* __restrict__ wsh, const __half* __restrict__ wsl,
                  const __half* __restrict__ wnh, const __half* __restrict__ wnl,
                  const float* __restrict__ bias, float* __restrict__ S,
                  __half* __restrict__ P, int n, int ntiles) {
    extern __shared__ char smem[];
    constexpr int NB = 64 * 256;
    constexpr int WBASE = 16384;
    const uint32_t sb = smem_to_u32(smem);
    const uint32_t wb = sb + WBASE;
    const int t = threadIdx.x, lane = t & 31, wid = t >> 5;

    load_swz(wsh, smem + WBASE,          64, t);
    load_swz(wsl, smem + WBASE + NB,     64, t);
    load_swz(wnh, smem + WBASE + 2 * NB, 64, t);
    load_swz(wnl, smem + WBASE + 3 * NB, 64, t);

    const int rhalf = (wid & 1) * 16;
    const int n0 = (wid >> 1) * 16;
    const int arowl = rhalf + (lane & 15);
    const int akh = lane >> 4;
    const int browl = ((lane >> 4) << 3) + (lane & 7);
    const int bkh = (lane >> 3) & 1;
    const int brow = n0 + browl;

    float breg[2][2];
#pragma unroll
    for (int nt = 0; nt < 2; ++nt) {
        int c = n0 + nt * 8 + (lane & 3) * 2;
        breg[nt][0] = __ldg(bias + c);
        breg[nt][1] = __ldg(bias + c + 1);
    }

    int tile = blockIdx.x, buf = 0;
    issue_1(xf, tile * 32, n, sb, t);
    CP_COMMIT();

    for (; tile < ntiles; tile += gridDim.x) {
        const int nxt = tile + gridDim.x;
        if (nxt < ntiles) {
            issue_1(xf, nxt * 32, n, sb + (uint32_t)(buf ^ 1) * 8192u, t);
            CP_COMMIT();
            CP_WAIT1();
        } else {
            CP_WAIT0();
        }
        __syncthreads();

        const uint32_t ab = sb + (uint32_t)buf * 8192u;
        float accS[2][4], accP[2][4];
#pragma unroll
        for (int q = 0; q < 2; ++q) {
            accS[q][0] = accS[q][1] = accS[q][2] = accS[q][3] = 0.f;
            accP[q][0] = accP[q][1] = accP[q][2] = accP[q][3] = 0.f;
        }

#pragma unroll
        for (int ks = 0; ks < 8; ++ks) {
            uint32_t ac = (uint32_t)((2 * ks + akh) ^ (arowl & 7));
            uint32_t aoff = (uint32_t)arowl * 256u + (ac << 4);
            uint32_t A[4];
            ldsm_x4(A, ab + aoff);
            uint32_t bc = (uint32_t)((2 * ks + bkh) ^ (brow & 7));
            uint32_t boff = (uint32_t)brow * 256u + (bc << 4);
            uint32_t Bsh[4], Bsl[4], Bnh[4], Bnl[4];
            ldsm_x4(Bsh, wb + boff);
            ldsm_x4(Bsl, wb + (uint32_t)NB + boff);
            ldsm_x4(Bnh, wb + (uint32_t)(2 * NB) + boff);
            ldsm_x4(Bnl, wb + (uint32_t)(3 * NB) + boff);
            mma_f16(accS[0], A, Bsh);  mma_f16(accS[1], A, Bsh + 2);
            mma_f16(accP[0], A, Bnh);  mma_f16(accP[1], A, Bnh + 2);
            mma_f16(accS[0], A, Bsl);  mma_f16(accS[1], A, Bsl + 2);
            mma_f16(accP[0], A, Bnl);  mma_f16(accP[1], A, Bnl + 2);
        }

        const int r0 = tile * 32 + rhalf + (lane >> 2);
        const int r1 = r0 + 8;
#pragma unroll
        for (int nt = 0; nt < 2; ++nt) {
            int c = n0 + nt * 8 + (lane & 3) * 2;
            if (r0 < n) {
                *reinterpret_cast<float2*>(S + (size_t)r0 * 64 + c) =
                    make_float2(accS[nt][0] + breg[nt][0], accS[nt][1] + breg[nt][1]);
                *reinterpret_cast<__half2*>(P + (size_t)r0 * 64 + c) =
                    __floats2half2_rn(accP[nt][0], accP[nt][1]);
            }
            if (r1 < n) {
                *reinterpret_cast<float2*>(S + (size_t)r1 * 64 + c) =
                    make_float2(accS[nt][2] + breg[nt][0], accS[nt][3] + breg[nt][1]);
                *reinterpret_cast<__half2*>(P + (size_t)r1 * 64 + c) =
                    __floats2half2_rn(accP[nt][2], accP[nt][3]);
            }
        }
        __syncthreads();
        buf ^= 1;
    }
}

// ---------------- launch ----------------
extern "C" void kernel_launch(void* const* d_in, const int* in_sizes, int n_in,
                              void* d_out, int out_size) {
    const float* x   = (const float*)d_in[0];
    const int*   src = (const int*)d_in[1];
    const int*   dst = (const int*)d_in[2];
    const float* Ws1 = (const float*)d_in[3];
    const float* b1  = (const float*)d_in[4];
    const float* Wn1 = (const float*)d_in[5];
    const float* Ws2 = (const float*)d_in[6];
    const float* b2  = (const float*)d_in[7];
    const float* Wn2 = (const float*)d_in[8];
    const float* Ws3 = (const float*)d_in[9];
    const float* b3  = (const float*)d_in[10];
    const float* Wn3 = (const float*)d_in[11];

    const int N = in_sizes[0] / DIM;
    const int E = in_sizes[1];
    float* out = (float*)d_out;

    int *deg_i, *rowptr, *csr;
    float *invdeg, *S1, *S3;
    __half *P16, *xf16, *hf16, *agg16, *wth, *wtl;
    cudaGetSymbolAddress((void**)&deg_i,  g_deg_i);
    cudaGetSymbolAddress((void**)&rowptr, g_rowptr);
    cudaGetSymbolAddress((void**)&csr,    g_csr);
    cudaGetSymbolAddress((void**)&invdeg, g_invdeg);
    cudaGetSymbolAddress((void**)&S1,     g_S1);
    cudaGetSymbolAddress((void**)&S3,     g_S3);
    cudaGetSymbolAddress((void**)&P16,    g_P16);
    cudaGetSymbolAddress((void**)&xf16,   g_xf16);
    cudaGetSymbolAddress((void**)&hf16,   g_hf16);
    cudaGetSymbolAddress((void**)&agg16,  g_agg16);
    cudaGetSymbolAddress((void**)&wth,    g_wth);
    cudaGetSymbolAddress((void**)&wtl,    g_wtl);

    // one-time host-side setup (runs on the non-captured correctness call first)
    static cudaStream_t s1 = nullptr;
    static cudaEvent_t evf, evsp, ea1;
    if (!s1) {
        cudaStreamCreateWithFlags(&s1, cudaStreamNonBlocking);
        cudaEventCreateWithFlags(&evf,  cudaEventDisableTiming);
        cudaEventCreateWithFlags(&evsp, cudaEventDisableTiming);
        cudaEventCreateWithFlags(&ea1,  cudaEventDisableTiming);
    }

    const int SMF = 32768 + 4 * 128 * 256;   // 163840 (fused layer 2)
    const int SMH = 16384 + 2 * 128 * 256;   // 81920  (half GEMMs)
    const int SM3 = 16384 + 4 * 64 * 256;    // 81920  (layer-3 dual)
    cudaFuncSetAttribute(gemm_kernel<128>,
                         cudaFuncAttributeMaxDynamicSharedMemorySize, SMF);
    cudaFuncSetAttribute(gemm_half_kernel<128, 0>,
                         cudaFuncAttributeMaxDynamicSharedMemorySize, SMH);
    cudaFuncSetAttribute(gemm_half_kernel<128, 1>,
                         cudaFuncAttributeMaxDynamicSharedMemorySize, SMH);
    cudaFuncSetAttribute(gemm3_dual_kernel,
                         cudaFuncAttributeMaxDynamicSharedMemorySize, SM3);

    const int nb_edges = (E + 255) / 256;
    const int nb_agg   = (int)(((long long)N * 32 + 255) / 256);
    const int nb_aadd  = (int)(((long long)N * 16 + 255) / 256);
    const int ntiles   = (N + 31) / 32;
    const int GRID     = 152;
    const int n2       = N * DIM / 2;
    const int nb_conv  = (n2 + 81920 + 255) / 256;

    // ---- fork: s1 builds CSR while s0 does conversions; agg1 (s1) waits on the convert ----
    cudaEventRecord(evf, 0);
    cudaStreamWaitEvent(s1, evf, 0);

    // deg_i is all-zero at entry (zero-init + fill_csr countdown restores it)
    deg_kernel<<<nb_edges, 256, 0, s1>>>(dst, deg_i, E);
    scan_kernel<<<1, 1024, 0, s1>>>(deg_i, rowptr, invdeg, N);
    fill_csr_kernel<<<nb_edges, 256, 0, s1>>>(src, dst, rowptr, deg_i, csr, E);

    convert_kernel<<<nb_conv, 256>>>(x, xf16, n2, Ws1, Wn1, Ws2, Wn2, Ws3, Wn3, wth, wtl);
    cudaEventRecord(evsp, 0);

    cudaStreamWaitEvent(s1, evsp, 0);
    agg_kernel<<<nb_agg, 256, 0, s1>>>(xf16, rowptr, csr, invdeg, agg16, N);
    cudaEventRecord(ea1, s1);

    // s0: layer-1 self GEMM overlaps with CSR + agg1
    gemm_half_kernel<128, 0><<<GRID, 256, SMH>>>(
        xf16, wth + 0 * 16384, wtl + 0 * 16384, b1, S1, nullptr, N, ntiles);

    // ---- join: layer-1 neigh + the rest run single-stream ----
    cudaStreamWaitEvent(0, ea1, 0);
    gemm_half_kernel<128, 1><<<GRID, 256, SMH>>>(
        agg16, wth + 1 * 16384, wtl + 1 * 16384, S1, nullptr, hf16, N, ntiles);

    // Layer 2 (fused)
    agg_kernel<<<nb_agg, 256>>>(hf16, rowptr, csr, invdeg, agg16, N);
    gemm_kernel<128><<<GRID, 256, SMF>>>(
        hf16, agg16,
        wth + 2 * 16384, wtl + 2 * 16384, wth + 3 * 16384, wtl + 3 * 16384,
        b2, hf16, N, ntiles);

    // Layer 3: lin-before-mp (matches reference)
    gemm3_dual_kernel<<<GRID, 256, SM3>>>(
        hf16,
        wth + 4 * 16384, wtl + 4 * 16384, wth + 5 * 16384, wtl + 5 * 16384,
        b3, S3, P16, N, ntiles);
    aggadd_kernel<<<nb_aadd, 256>>>(S3, P16, rowptr, csr, invdeg, out, N);
}